// round 3
// baseline (speedup 1.0000x reference)
#include <cuda_runtime.h>
#include <math.h>
#include <stdint.h>

#define BSZ 16
#define SEQ 512
#define DM  512
#define DI  1024
#define DS  32
#define NTOK (BSZ*SEQ)        // 8192
#define KEMB 112              // 96 (conv im2col) + 4 (mark) + 12 zero pad -> %16==0
#define PRED 1024

// ---------------- scratch (static device globals; no runtime alloc) -------------
__device__ float g_emb [NTOK*DM];
__device__ float g_xz  [(size_t)NTOK*2*DI];
__device__ float g_x   [NTOK*DI];
__device__ float g_xdbc[NTOK*96];
__device__ float g_dt  [NTOK*DI];
__device__ float g_y   [NTOK*DI];
__device__ float g_mo  [NTOK*DM];
__device__ float g_cur [NTOK*DM];
__device__ float g_outs[(size_t)BSZ*PRED*DM];
__device__ float g_pe  [SEQ*DM];
__device__ float g_im  [NTOK*KEMB];
__device__ float g_wemb[DM*KEMB];

// ---------------- positional embedding (double precision, one-time) -------------
__global__ void pe_kernel(float* __restrict__ pe) {
    int idx = blockIdx.x * blockDim.x + threadIdx.x;
    if (idx >= SEQ*DM) return;
    int t = idx >> 9;           // /512
    int o = idx & 511;
    int j2 = o & ~1;
    double div = exp(-(double)j2 * (log(10000.0) / (double)DM));
    double ang = (double)t * div;
    pe[idx] = (float)((o & 1) ? cos(ang) : sin(ang));
}

// ---------------- im2col for the embed conv (+marks, zero pad) ------------------
__global__ void im2col_kernel(float* __restrict__ im,
                              const float* __restrict__ x_enc,
                              const float* __restrict__ x_mark) {
    int idx = blockIdx.x * blockDim.x + threadIdx.x;
    if (idx >= NTOK*KEMB) return;
    int n = idx / KEMB;
    int c = idx - n*KEMB;
    int b = n >> 9, t = n & 511;
    float v = 0.f;
    if (c < 96) {
        int k = c >> 5;            // 0..2
        int i = c & 31;
        int tt = t + k - 2; if (tt < 0) tt = 0;
        v = x_enc[(size_t)(b*SEQ + tt)*32 + i];
    } else if (c < 100) {
        v = x_mark[(size_t)n*4 + (c - 96)];
    }
    im[idx] = v;
}

__global__ void wemb_kernel(float* __restrict__ wemb,
                            const float* __restrict__ conv_w,
                            const float* __restrict__ temp_w) {
    int idx = blockIdx.x * blockDim.x + threadIdx.x;
    if (idx >= DM*KEMB) return;
    int o = idx / KEMB;
    int c = idx - o*KEMB;
    float v = 0.f;
    if (c < 96) {
        int k = c >> 5;
        int i = c & 31;
        v = conv_w[(size_t)(o*32 + i)*3 + k];
    } else if (c < 100) {
        v = temp_w[o*4 + (c - 96)];
    }
    wemb[idx] = v;
}

// ---------------- generic tiled GEMM: C[M,N] = A[M,K(lda)] * W[N,K]^T -----------
// EP: 0 = none, 1 = +bias then softplus, 2 = += aux[(m%512)*N + n]
template<int EP>
__global__ void __launch_bounds__(256)
gemm_tn(const float* __restrict__ A, int lda,
        const float* __restrict__ W,
        const float* __restrict__ bias,
        const float* __restrict__ aux,
        float* __restrict__ C,
        int M, int N, int K)
{
    __shared__ __align__(16) float As[16][68];
    __shared__ __align__(16) float Ws[16][68];
    const int tx = threadIdx.x & 15;
    const int ty = threadIdx.x >> 4;
    const int m0 = blockIdx.y * 64;
    const int n0 = blockIdx.x * 64;
    const int lr = threadIdx.x >> 2;        // 0..63
    const int lc = (threadIdx.x & 3) * 4;   // 0,4,8,12

    float c[4][4];
    #pragma unroll
    for (int i = 0; i < 4; ++i)
        #pragma unroll
        for (int j = 0; j < 4; ++j) c[i][j] = 0.f;

    for (int k0 = 0; k0 < K; k0 += 16) {
        float4 av = make_float4(0.f,0.f,0.f,0.f);
        int am = m0 + lr;
        if (am < M) av = *(const float4*)(A + (size_t)am*lda + k0 + lc);
        As[lc+0][lr] = av.x; As[lc+1][lr] = av.y;
        As[lc+2][lr] = av.z; As[lc+3][lr] = av.w;

        float4 wv = make_float4(0.f,0.f,0.f,0.f);
        int wn = n0 + lr;
        if (wn < N) wv = *(const float4*)(W + (size_t)wn*K + k0 + lc);
        Ws[lc+0][lr] = wv.x; Ws[lc+1][lr] = wv.y;
        Ws[lc+2][lr] = wv.z; Ws[lc+3][lr] = wv.w;
        __syncthreads();

        #pragma unroll
        for (int kk = 0; kk < 16; ++kk) {
            float4 a4 = *(const float4*)&As[kk][ty*4];
            float4 b4 = *(const float4*)&Ws[kk][tx*4];
            c[0][0] = fmaf(a4.x, b4.x, c[0][0]);
            c[0][1] = fmaf(a4.x, b4.y, c[0][1]);
            c[0][2] = fmaf(a4.x, b4.z, c[0][2]);
            c[0][3] = fmaf(a4.x, b4.w, c[0][3]);
            c[1][0] = fmaf(a4.y, b4.x, c[1][0]);
            c[1][1] = fmaf(a4.y, b4.y, c[1][1]);
            c[1][2] = fmaf(a4.y, b4.z, c[1][2]);
            c[1][3] = fmaf(a4.y, b4.w, c[1][3]);
            c[2][0] = fmaf(a4.z, b4.x, c[2][0]);
            c[2][1] = fmaf(a4.z, b4.y, c[2][1]);
            c[2][2] = fmaf(a4.z, b4.z, c[2][2]);
            c[2][3] = fmaf(a4.z, b4.w, c[2][3]);
            c[3][0] = fmaf(a4.w, b4.x, c[3][0]);
            c[3][1] = fmaf(a4.w, b4.y, c[3][1]);
            c[3][2] = fmaf(a4.w, b4.z, c[3][2]);
            c[3][3] = fmaf(a4.w, b4.w, c[3][3]);
        }
        __syncthreads();
    }

    #pragma unroll
    for (int i = 0; i < 4; ++i) {
        int m = m0 + ty*4 + i;
        if (m >= M) continue;
        #pragma unroll
        for (int j = 0; j < 4; ++j) {
            int n = n0 + tx*4 + j;
            if (n >= N) continue;
            float v = c[i][j];
            if (EP == 1) {
                v += bias[n];
                v = (v > 20.f) ? v : log1pf(__expf(v));
            } else if (EP == 2) {
                v += aux[(size_t)(m & 511)*N + n];
            }
            C[(size_t)m*N + n] = v;
        }
    }
}

// ---------------- depthwise causal conv1d (k=4) + SiLU --------------------------
__global__ void conv_silu_kernel(const float* __restrict__ xz,
                                 const float* __restrict__ w,
                                 const float* __restrict__ bias,
                                 float* __restrict__ out)
{
    int idx = blockIdx.x * blockDim.x + threadIdx.x;
    if (idx >= NTOK*DI) return;
    int d = idx & (DI-1);
    int n = idx >> 10;
    int t = n & 511;
    float s = bias[d];
    const float* wd = w + d*4;
    #pragma unroll
    for (int k = 0; k < 4; ++k) {
        int tau = t - 3 + k;
        if (tau >= 0)
            s = fmaf(wd[k], xz[(size_t)(n + k - 3)*(2*DI) + d], s);
    }
    float sil = s / (1.f + __expf(-s));
    out[idx] = sil;
}

// ---------------- selective scan (fused D-skip + z-gate) ------------------------
// 4 lanes per (b,d), 8 states each. block 512 threads = 128 channels, grid (8,16).
#define SCAN_STEP(J, BB, CC) { \
    float dA = __expf(dtv * a[J]); \
    h[J] = fmaf(dA, h[J], kk * (BB)); \
    acc = fmaf(h[J], (CC), acc); }

__global__ void __launch_bounds__(512)
scan_kernel(const float* __restrict__ dt_,
            const float* __restrict__ xdbc,
            const float* __restrict__ x_,
            const float* __restrict__ xz,
            const float* __restrict__ A_log,
            const float* __restrict__ Dv,
            float* __restrict__ y_)
{
    const int b    = blockIdx.y;
    const int grp  = threadIdx.x >> 2;        // 0..127
    const int l4   = threadIdx.x & 3;
    const int d    = blockIdx.x * 128 + grp;
    const int s0   = l4 * 8;

    float a[8];
    #pragma unroll
    for (int j = 0; j < 8; ++j)
        a[j] = -__expf(A_log[d*DS + s0 + j]);

    float h[8];
    #pragma unroll
    for (int j = 0; j < 8; ++j) h[j] = 0.f;

    const float Dd = Dv[d];
    const float* dtp = dt_ + (size_t)b*SEQ*DI + d;
    const float* xp  = x_  + (size_t)b*SEQ*DI + d;
    const float* zp  = xz  + (size_t)b*SEQ*(2*DI) + DI + d;
    const float* bc  = xdbc + (size_t)b*SEQ*96;
    float*       yp  = y_  + (size_t)b*SEQ*DI + d;

    // prefetch t=0
    float dtv = dtp[0];
    float xv  = xp[0];
    float zv  = zp[0];
    float4 B0 = *(const float4*)(bc + 32 + s0);
    float4 B1 = *(const float4*)(bc + 36 + s0);
    float4 C0 = *(const float4*)(bc + 64 + s0);
    float4 C1 = *(const float4*)(bc + 68 + s0);

    for (int t = 0; t < SEQ; ++t) {
        int tn = (t + 1 < SEQ) ? t + 1 : t;
        float dtv_n = dtp[(size_t)tn*DI];
        float xv_n  = xp[(size_t)tn*DI];
        float zv_n  = zp[(size_t)tn*(2*DI)];
        float4 B0n = *(const float4*)(bc + tn*96 + 32 + s0);
        float4 B1n = *(const float4*)(bc + tn*96 + 36 + s0);
        float4 C0n = *(const float4*)(bc + tn*96 + 64 + s0);
        float4 C1n = *(const float4*)(bc + tn*96 + 68 + s0);

        float kk = dtv * xv;
        float acc = 0.f;
        SCAN_STEP(0, B0.x, C0.x)
        SCAN_STEP(1, B0.y, C0.y)
        SCAN_STEP(2, B0.z, C0.z)
        SCAN_STEP(3, B0.w, C0.w)
        SCAN_STEP(4, B1.x, C1.x)
        SCAN_STEP(5, B1.y, C1.y)
        SCAN_STEP(6, B1.z, C1.z)
        SCAN_STEP(7, B1.w, C1.w)

        acc += __shfl_xor_sync(0xffffffffu, acc, 1);
        acc += __shfl_xor_sync(0xffffffffu, acc, 2);

        if (l4 == 0) {
            float sil = zv / (1.f + __expf(-zv));
            yp[(size_t)t*DI] = (acc + xv * Dd) * sil;
        }
        dtv = dtv_n; xv = xv_n; zv = zv_n;
        B0 = B0n; B1 = B1n; C0 = C0n; C1 = C1n;
    }
}

// ---------------- layernorm (row = 512), dual write (cur + outs slice) ----------
__global__ void __launch_bounds__(128)
ln_kernel(const float* __restrict__ in,
          const float* __restrict__ w,
          const float* __restrict__ bsrc,
          float* __restrict__ cur,
          float* __restrict__ outs,
          int it)
{
    int r = blockIdx.x;
    int tid = threadIdx.x;
    const float* row = in + (size_t)r*DM;
    float4 v = *(const float4*)(row + tid*4);
    float s  = v.x + v.y + v.z + v.w;
    float sq = v.x*v.x + v.y*v.y + v.z*v.z + v.w*v.w;
    #pragma unroll
    for (int o = 16; o; o >>= 1) {
        s  += __shfl_xor_sync(0xffffffffu, s,  o);
        sq += __shfl_xor_sync(0xffffffffu, sq, o);
    }
    __shared__ float ss[4], ssq[4];
    if ((tid & 31) == 0) { ss[tid >> 5] = s; ssq[tid >> 5] = sq; }
    __syncthreads();
    s  = ss[0] + ss[1] + ss[2] + ss[3];
    sq = ssq[0] + ssq[1] + ssq[2] + ssq[3];
    float mean = s * (1.f/512.f);
    float var  = sq * (1.f/512.f) - mean*mean;
    float inv  = rsqrtf(var + 1e-5f);
    int b = r >> 9, t = r & 511;
    size_t orow = ((size_t)b*PRED + (size_t)it*SEQ + t)*DM;
    int c = tid*4;
    float4 wv = *(const float4*)(w + c);
    float4 bv = *(const float4*)(bsrc + c);
    float4 res;
    res.x = (v.x - mean)*inv*wv.x + bv.x;
    res.y = (v.y - mean)*inv*wv.y + bv.y;
    res.z = (v.z - mean)*inv*wv.z + bv.z;
    res.w = (v.w - mean)*inv*wv.w + bv.w;
    *(float4*)(cur + (size_t)r*DM + c) = res;
    *(float4*)(outs + orow + c) = res;
}

// ---------------- host launcher -------------------------------------------------
extern "C" void kernel_launch(void* const* d_in, const int* in_sizes, int n_in,
                              void* d_out, int out_size)
{
    (void)in_sizes; (void)n_in; (void)out_size;
    const float* x_enc      = (const float*)d_in[0];
    const float* x_mark_enc = (const float*)d_in[1];
    const float* conv_emb_w = (const float*)d_in[4];
    const float* temp_w     = (const float*)d_in[5];
    const float* in_proj_w  = (const float*)d_in[6];
    const float* conv1d_w   = (const float*)d_in[7];
    const float* conv1d_b   = (const float*)d_in[8];
    const float* x_proj_w   = (const float*)d_in[9];
    const float* dt_proj_w  = (const float*)d_in[10];
    const float* dt_proj_b  = (const float*)d_in[11];
    const float* A_log      = (const float*)d_in[12];
    const float* D_in       = (const float*)d_in[13];
    const float* out_proj_w = (const float*)d_in[14];
    const float* ln_w       = (const float*)d_in[15];
    const float* ln_b       = (const float*)d_in[16];
    const float* head_w     = (const float*)d_in[17];

    float *emb, *xz, *xb, *xdbc, *dtb, *yb, *mo, *cur, *outs, *pe, *im, *wemb;
    cudaGetSymbolAddress((void**)&emb,  g_emb);
    cudaGetSymbolAddress((void**)&xz,   g_xz);
    cudaGetSymbolAddress((void**)&xb,   g_x);
    cudaGetSymbolAddress((void**)&xdbc, g_xdbc);
    cudaGetSymbolAddress((void**)&dtb,  g_dt);
    cudaGetSymbolAddress((void**)&yb,   g_y);
    cudaGetSymbolAddress((void**)&mo,   g_mo);
    cudaGetSymbolAddress((void**)&cur,  g_cur);
    cudaGetSymbolAddress((void**)&outs, g_outs);
    cudaGetSymbolAddress((void**)&pe,   g_pe);
    cudaGetSymbolAddress((void**)&im,   g_im);
    cudaGetSymbolAddress((void**)&wemb, g_wemb);

    // ---- embedding ----
    pe_kernel<<<(SEQ*DM + 511)/512, 512>>>(pe);
    im2col_kernel<<<(NTOK*KEMB + 255)/256, 256>>>(im, x_enc, x_mark_enc);
    wemb_kernel<<<(DM*KEMB + 255)/256, 256>>>(wemb, conv_emb_w, temp_w);
    gemm_tn<2><<<dim3(DM/64, NTOK/64), 256>>>(im, KEMB, wemb, nullptr, pe, emb,
                                              NTOK, DM, KEMB);

    // ---- 2 mamba blocks ----
    const float* curin = emb;
    for (int it = 0; it < 2; ++it) {
        gemm_tn<0><<<dim3(2*DI/64, NTOK/64), 256>>>(curin, DM, in_proj_w, nullptr,
                                                    nullptr, xz, NTOK, 2*DI, DM);
        conv_silu_kernel<<<(NTOK*DI + 255)/256, 256>>>(xz, conv1d_w, conv1d_b, xb);
        gemm_tn<0><<<dim3(2, NTOK/64), 256>>>(xb, DI, x_proj_w, nullptr,
                                              nullptr, xdbc, NTOK, 96, DI);
        gemm_tn<1><<<dim3(DI/64, NTOK/64), 256>>>(xdbc, 96, dt_proj_w, dt_proj_b,
                                                  nullptr, dtb, NTOK, DI, 32);
        scan_kernel<<<dim3(DI/128, BSZ), 512>>>(dtb, xdbc, xb, xz, A_log, D_in, yb);
        gemm_tn<0><<<dim3(DM/64, NTOK/64), 256>>>(yb, DI, out_proj_w, nullptr,
                                                  nullptr, mo, NTOK, DM, DI);
        ln_kernel<<<NTOK, 128>>>(mo, ln_w, ln_b, cur, outs, it);
        curin = cur;
    }

    // ---- head ----
    gemm_tn<0><<<dim3(1, (BSZ*PRED)/64), 256>>>(outs, DM, head_w, nullptr, nullptr,
                                                (float*)d_out, BSZ*PRED, 32, DM);
}

// round 9
// speedup vs baseline: 1.1581x; 1.1581x over previous
#include <cuda_runtime.h>
#include <cuda_bf16.h>
#include <math.h>
#include <stdint.h>

#define BSZ 16
#define SEQ 512
#define DM  512
#define DI  1024
#define DS  32
#define NTOK (BSZ*SEQ)        // 8192
#define KEMB 112              // 96 (conv im2col) + 4 (mark) + 12 zero pad -> %16==0
#define PRED 1024

// ---------------- scratch (static device globals; no runtime alloc) -------------
__device__ float g_emb [NTOK*DM];
__device__ float g_xz  [(size_t)NTOK*2*DI];
__device__ float g_x   [NTOK*DI];
__device__ float g_xdbc[NTOK*96];
__device__ float g_dt  [NTOK*DI];
__device__ float g_y   [NTOK*DI];
__device__ float g_mo  [NTOK*DM];
__device__ float g_cur [NTOK*DM];
__device__ float g_outs[(size_t)BSZ*PRED*DM];
__device__ float g_pe  [SEQ*DM];
__device__ float g_im  [NTOK*KEMB];
__device__ float g_wemb[DM*KEMB];

// bf16 K3-concat buffers:  A3 = [hi | lo | hi],  W3 = [hi | hi | lo]
__device__ __nv_bfloat16 g_a3 [(size_t)NTOK*3*DI];          // up to 8192 x 3072
__device__ __nv_bfloat16 g_wi3[(size_t)2*DI*3*DM];          // 2048 x 1536
__device__ __nv_bfloat16 g_wo3[(size_t)DM*3*DI];            // 512 x 3072
__device__ __nv_bfloat16 g_wx3[(size_t)128*3*DI];           // 128(pad) x 3072

// ================= PTX helpers (baseline sm_80+ ISA only) =======================
__device__ __forceinline__ uint32_t smem_u32(const void* p) {
    uint32_t a;
    asm("{ .reg .u64 t; cvta.to.shared.u64 t, %1; cvt.u32.u64 %0, t; }" : "=r"(a) : "l"(p));
    return a;
}
#define CP_ASYNC16(dst, src) \
    asm volatile("cp.async.cg.shared.global [%0], [%1], 16;" :: "r"(dst), "l"(src))
#define CP_COMMIT() asm volatile("cp.async.commit_group;" ::: "memory")
#define CP_WAIT(n)  asm volatile("cp.async.wait_group %0;" :: "n"(n) : "memory")

// ---------------- fp32 -> bf16 hi/lo 3-way K-concat splits ----------------------
__global__ void split3A_kernel(const float* __restrict__ in,
                               __nv_bfloat16* __restrict__ out, int MK, int K)
{
    int i = blockIdx.x * blockDim.x + threadIdx.x;
    if (i >= MK) return;
    int m = i / K, k = i - m*K;
    float v = in[i];
    __nv_bfloat16 h = __float2bfloat16(v);
    __nv_bfloat16 l = __float2bfloat16(v - __bfloat162float(h));
    size_t base = (size_t)m*3*K + k;
    out[base]       = h;
    out[base + K]   = l;
    out[base + 2*K] = h;
}
__global__ void split3W_kernel(const float* __restrict__ in,
                               __nv_bfloat16* __restrict__ out,
                               int N, int Npad, int K)
{
    int i = blockIdx.x * blockDim.x + threadIdx.x;
    if (i >= Npad*K) return;
    int n = i / K, k = i - n*K;
    float v = (n < N) ? in[(size_t)n*K + k] : 0.f;
    __nv_bfloat16 h = __float2bfloat16(v);
    __nv_bfloat16 l = __float2bfloat16(v - __bfloat162float(h));
    size_t base = (size_t)n*3*K + k;
    out[base]       = h;
    out[base + K]   = h;
    out[base + 2*K] = l;
}

// ---------------- warp-mma bf16 GEMM: C[M,N] = A3[M,K3] * W3[N,K3]^T ------------
// CTA tile 128x128, 8 warps (warp tile 64x32). K chunks of 64 bf16, XOR-swizzled
// SMEM, cp.async double buffer, ldmatrix operand loads, fp32 register accum.
__global__ void __launch_bounds__(256)
gemm_mma(const __nv_bfloat16* __restrict__ A, const __nv_bfloat16* __restrict__ W,
         float* __restrict__ C, int K3, int ldc, int nvalid)
{
    extern __shared__ char sm[];
    const uint32_t sbase = smem_u32(sm);
    const int tid  = threadIdx.x, lane = tid & 31, wid = tid >> 5;
    const int m0 = blockIdx.y * 128, n0 = blockIdx.x * 128;
    const int wm = (wid >> 2) * 64, wn = (wid & 3) * 32;
    const int NC = K3 >> 6;

    float acc[4][4][4];
    #pragma unroll
    for (int i = 0; i < 4; ++i)
        #pragma unroll
        for (int j = 0; j < 4; ++j)
            #pragma unroll
            for (int q = 0; q < 4; ++q) acc[i][j][q] = 0.f;

    // stage s: A tile at s*32768, W tile at s*32768 + 16384 (each 128 rows x 128B)
    auto issue = [&](int c, int s) {
        uint32_t sA = sbase + s*32768;
        uint32_t sW = sA + 16384;
        #pragma unroll
        for (int i = 0; i < 4; ++i) {
            int u = tid + i*256;
            int r = u >> 3, un = u & 7;
            uint32_t d = sA + r*128 + ((un ^ (r & 7)) << 4);
            CP_ASYNC16(d, A + (size_t)(m0 + r)*K3 + c*64 + un*8);
        }
        #pragma unroll
        for (int i = 0; i < 4; ++i) {
            int u = tid + i*256;
            int r = u >> 3, un = u & 7;
            uint32_t d = sW + r*128 + ((un ^ (r & 7)) << 4);
            CP_ASYNC16(d, W + (size_t)(n0 + r)*K3 + c*64 + un*8);
        }
        CP_COMMIT();
    };

    issue(0, 0);
    for (int c = 0; c < NC; ++c) {
        int s = c & 1;
        if (c + 1 < NC) { issue(c + 1, s ^ 1); CP_WAIT(1); }
        else            { CP_WAIT(0); }
        __syncthreads();

        uint32_t sA = sbase + s*32768;
        uint32_t sW = sA + 16384;
        #pragma unroll
        for (int ks = 0; ks < 4; ++ks) {
            uint32_t a[4][4];
            #pragma unroll
            for (int mt = 0; mt < 4; ++mt) {
                int r  = wm + mt*16 + (lane & 15);
                int un = ks*2 + (lane >> 4);
                uint32_t ad = sA + r*128 + ((un ^ (r & 7)) << 4);
                asm volatile("ldmatrix.sync.aligned.m8n8.x4.shared.b16 {%0,%1,%2,%3}, [%4];"
                    : "=r"(a[mt][0]), "=r"(a[mt][1]), "=r"(a[mt][2]), "=r"(a[mt][3])
                    : "r"(ad));
            }
            uint32_t b[4][2];
            #pragma unroll
            for (int p = 0; p < 2; ++p) {
                int n  = wn + p*16 + (lane & 7) + ((lane >> 4) << 3);
                int un = ks*2 + ((lane >> 3) & 1);
                uint32_t bd = sW + n*128 + ((un ^ (n & 7)) << 4);
                asm volatile("ldmatrix.sync.aligned.m8n8.x4.shared.b16 {%0,%1,%2,%3}, [%4];"
                    : "=r"(b[p*2][0]), "=r"(b[p*2][1]), "=r"(b[p*2+1][0]), "=r"(b[p*2+1][1])
                    : "r"(bd));
            }
            #pragma unroll
            for (int mt = 0; mt < 4; ++mt)
                #pragma unroll
                for (int nt = 0; nt < 4; ++nt)
                    asm volatile(
                        "mma.sync.aligned.m16n8k16.row.col.f32.bf16.bf16.f32 "
                        "{%0,%1,%2,%3}, {%4,%5,%6,%7}, {%8,%9}, {%0,%1,%2,%3};"
                        : "+f"(acc[mt][nt][0]), "+f"(acc[mt][nt][1]),
                          "+f"(acc[mt][nt][2]), "+f"(acc[mt][nt][3])
                        : "r"(a[mt][0]), "r"(a[mt][1]), "r"(a[mt][2]), "r"(a[mt][3]),
                          "r"(b[nt][0]), "r"(b[nt][1]));
        }
        __syncthreads();
    }

    // epilogue: c0,c1 -> row lane>>2, cols (lane&3)*2..+1; c2,c3 -> row +8
    #pragma unroll
    for (int mt = 0; mt < 4; ++mt) {
        int r0 = m0 + wm + mt*16 + (lane >> 2);
        #pragma unroll
        for (int nt = 0; nt < 4; ++nt) {
            int col = n0 + wn + nt*8 + (lane & 3)*2;
            if (col < nvalid) {
                *(float2*)(C + (size_t)r0*ldc + col) =
                    make_float2(acc[mt][nt][0], acc[mt][nt][1]);
                *(float2*)(C + (size_t)(r0+8)*ldc + col) =
                    make_float2(acc[mt][nt][2], acc[mt][nt][3]);
            }
        }
    }
}

// ---------------- positional embedding (double precision, one-time) -------------
__global__ void pe_kernel(float* __restrict__ pe) {
    int idx = blockIdx.x * blockDim.x + threadIdx.x;
    if (idx >= SEQ*DM) return;
    int t = idx >> 9;
    int o = idx & 511;
    int j2 = o & ~1;
    double div = exp(-(double)j2 * (log(10000.0) / (double)DM));
    double ang = (double)t * div;
    pe[idx] = (float)((o & 1) ? cos(ang) : sin(ang));
}

// ---------------- im2col for the embed conv (+marks, zero pad) ------------------
__global__ void im2col_kernel(float* __restrict__ im,
                              const float* __restrict__ x_enc,
                              const float* __restrict__ x_mark) {
    int idx = blockIdx.x * blockDim.x + threadIdx.x;
    if (idx >= NTOK*KEMB) return;
    int n = idx / KEMB;
    int c = idx - n*KEMB;
    int b = n >> 9, t = n & 511;
    float v = 0.f;
    if (c < 96) {
        int k = c >> 5;
        int i = c & 31;
        int tt = t + k - 2; if (tt < 0) tt = 0;
        v = x_enc[(size_t)(b*SEQ + tt)*32 + i];
    } else if (c < 100) {
        v = x_mark[(size_t)n*4 + (c - 96)];
    }
    im[idx] = v;
}

__global__ void wemb_kernel(float* __restrict__ wemb,
                            const float* __restrict__ conv_w,
                            const float* __restrict__ temp_w) {
    int idx = blockIdx.x * blockDim.x + threadIdx.x;
    if (idx >= DM*KEMB) return;
    int o = idx / KEMB;
    int c = idx - o*KEMB;
    float v = 0.f;
    if (c < 96) {
        int k = c >> 5;
        int i = c & 31;
        v = conv_w[(size_t)(o*32 + i)*3 + k];
    } else if (c < 100) {
        v = temp_w[o*4 + (c - 96)];
    }
    wemb[idx] = v;
}

// ---------------- SIMT tiled GEMM (small GEMMs): C = A * W^T --------------------
// EP: 0 = none, 1 = +bias then softplus, 2 = += aux[(m%512)*N + n]
template<int EP>
__global__ void __launch_bounds__(256)
gemm_tn(const float* __restrict__ A, int lda,
        const float* __restrict__ W,
        const float* __restrict__ bias,
        const float* __restrict__ aux,
        float* __restrict__ C,
        int M, int N, int K)
{
    __shared__ __align__(16) float As[16][68];
    __shared__ __align__(16) float Ws[16][68];
    const int tx = threadIdx.x & 15;
    const int ty = threadIdx.x >> 4;
    const int m0 = blockIdx.y * 64;
    const int n0 = blockIdx.x * 64;
    const int lr = threadIdx.x >> 2;
    const int lc = (threadIdx.x & 3) * 4;

    float c[4][4];
    #pragma unroll
    for (int i = 0; i < 4; ++i)
        #pragma unroll
        for (int j = 0; j < 4; ++j) c[i][j] = 0.f;

    for (int k0 = 0; k0 < K; k0 += 16) {
        float4 av = make_float4(0.f,0.f,0.f,0.f);
        int am = m0 + lr;
        if (am < M) av = *(const float4*)(A + (size_t)am*lda + k0 + lc);
        As[lc+0][lr] = av.x; As[lc+1][lr] = av.y;
        As[lc+2][lr] = av.z; As[lc+3][lr] = av.w;

        float4 wv = make_float4(0.f,0.f,0.f,0.f);
        int wn = n0 + lr;
        if (wn < N) wv = *(const float4*)(W + (size_t)wn*K + k0 + lc);
        Ws[lc+0][lr] = wv.x; Ws[lc+1][lr] = wv.y;
        Ws[lc+2][lr] = wv.z; Ws[lc+3][lr] = wv.w;
        __syncthreads();

        #pragma unroll
        for (int kk = 0; kk < 16; ++kk) {
            float4 a4 = *(const float4*)&As[kk][ty*4];
            float4 b4 = *(const float4*)&Ws[kk][tx*4];
            c[0][0] = fmaf(a4.x, b4.x, c[0][0]);
            c[0][1] = fmaf(a4.x, b4.y, c[0][1]);
            c[0][2] = fmaf(a4.x, b4.z, c[0][2]);
            c[0][3] = fmaf(a4.x, b4.w, c[0][3]);
            c[1][0] = fmaf(a4.y, b4.x, c[1][0]);
            c[1][1] = fmaf(a4.y, b4.y, c[1][1]);
            c[1][2] = fmaf(a4.y, b4.z, c[1][2]);
            c[1][3] = fmaf(a4.y, b4.w, c[1][3]);
            c[2][0] = fmaf(a4.z, b4.x, c[2][0]);
            c[2][1] = fmaf(a4.z, b4.y, c[2][1]);
            c[2][2] = fmaf(a4.z, b4.z, c[2][2]);
            c[2][3] = fmaf(a4.z, b4.w, c[2][3]);
            c[3][0] = fmaf(a4.w, b4.x, c[3][0]);
            c[3][1] = fmaf(a4.w, b4.y, c[3][1]);
            c[3][2] = fmaf(a4.w, b4.z, c[3][2]);
            c[3][3] = fmaf(a4.w, b4.w, c[3][3]);
        }
        __syncthreads();
    }

    #pragma unroll
    for (int i = 0; i < 4; ++i) {
        int m = m0 + ty*4 + i;
        if (m >= M) continue;
        #pragma unroll
        for (int j = 0; j < 4; ++j) {
            int n = n0 + tx*4 + j;
            if (n >= N) continue;
            float v = c[i][j];
            if (EP == 1) {
                v += bias[n];
                v = (v > 20.f) ? v : log1pf(__expf(v));
            } else if (EP == 2) {
                v += aux[(size_t)(m & 511)*N + n];
            }
            C[(size_t)m*N + n] = v;
        }
    }
}

// ---------------- depthwise causal conv1d (k=4) + SiLU --------------------------
__global__ void conv_silu_kernel(const float* __restrict__ xz,
                                 const float* __restrict__ w,
                                 const float* __restrict__ bias,
                                 float* __restrict__ out)
{
    int idx = blockIdx.x * blockDim.x + threadIdx.x;
    if (idx >= NTOK*DI) return;
    int d = idx & (DI-1);
    int n = idx >> 10;
    int t = n & 511;
    float s = bias[d];
    const float* wd = w + d*4;
    #pragma unroll
    for (int k = 0; k < 4; ++k) {
        int tau = t - 3 + k;
        if (tau >= 0)
            s = fmaf(wd[k], xz[(size_t)(n + k - 3)*(2*DI) + d], s);
    }
    float sil = s / (1.f + __expf(-s));
    out[idx] = sil;
}

// ---------------- selective scan (fused D-skip + z-gate) ------------------------
#define SCAN_STEP(J, BB, CC) { \
    float dA = __expf(dtv * a[J]); \
    h[J] = fmaf(dA, h[J], kk * (BB)); \
    acc = fmaf(h[J], (CC), acc); }

__global__ void __launch_bounds__(512)
scan_kernel(const float* __restrict__ dt_,
            const float* __restrict__ xdbc,
            const float* __restrict__ x_,
            const float* __restrict__ xz,
            const float* __restrict__ A_log,
            const float* __restrict__ Dv,
            float* __restrict__ y_)
{
    const int b    = blockIdx.y;
    const int grp  = threadIdx.x >> 2;
    const int l4   = threadIdx.x & 3;
    const int d    = blockIdx.x * 128 + grp;
    const int s0   = l4 * 8;

    float a[8];
    #pragma unroll
    for (int j = 0; j < 8; ++j)
        a[j] = -__expf(A_log[d*DS + s0 + j]);

    float h[8];
    #pragma unroll
    for (int j = 0; j < 8; ++j) h[j] = 0.f;

    const float Dd = Dv[d];
    const float* dtp = dt_ + (size_t)b*SEQ*DI + d;
    const float* xp  = x_  + (size_t)b*SEQ*DI + d;
    const float* zp  = xz  + (size_t)b*SEQ*(2*DI) + DI + d;
    const float* bc  = xdbc + (size_t)b*SEQ*96;
    float*       yp  = y_  + (size_t)b*SEQ*DI + d;

    float dtv = dtp[0];
    float xv  = xp[0];
    float zv  = zp[0];
    float4 B0 = *(const float4*)(bc + 32 + s0);
    float4 B1 = *(const float4*)(bc + 36 + s0);
    float4 C0 = *(const float4*)(bc + 64 + s0);
    float4 C1 = *(const float4*)(bc + 68 + s0);

    for (int t = 0; t < SEQ; ++t) {
        int tn = (t + 1 < SEQ) ? t + 1 : t;
        float dtv_n = dtp[(size_t)tn*DI];
        float xv_n  = xp[(size_t)tn*DI];
        float zv_n  = zp[(size_t)tn*(2*DI)];
        float4 B0n = *(const float4*)(bc + tn*96 + 32 + s0);
        float4 B1n = *(const float4*)(bc + tn*96 + 36 + s0);
        float4 C0n = *(const float4*)(bc + tn*96 + 64 + s0);
        float4 C1n = *(const float4*)(bc + tn*96 + 68 + s0);

        float kk = dtv * xv;
        float acc = 0.f;
        SCAN_STEP(0, B0.x, C0.x)
        SCAN_STEP(1, B0.y, C0.y)
        SCAN_STEP(2, B0.z, C0.z)
        SCAN_STEP(3, B0.w, C0.w)
        SCAN_STEP(4, B1.x, C1.x)
        SCAN_STEP(5, B1.y, C1.y)
        SCAN_STEP(6, B1.z, C1.z)
        SCAN_STEP(7, B1.w, C1.w)

        acc += __shfl_xor_sync(0xffffffffu, acc, 1);
        acc += __shfl_xor_sync(0xffffffffu, acc, 2);

        if (l4 == 0) {
            float sil = zv / (1.f + __expf(-zv));
            yp[(size_t)t*DI] = (acc + xv * Dd) * sil;
        }
        dtv = dtv_n; xv = xv_n; zv = zv_n;
        B0 = B0n; B1 = B1n; C0 = C0n; C1 = C1n;
    }
}

// ---------------- layernorm (row = 512), dual write (cur + outs slice) ----------
__global__ void __launch_bounds__(128)
ln_kernel(const float* __restrict__ in,
          const float* __restrict__ w,
          const float* __restrict__ bsrc,
          float* __restrict__ cur,
          float* __restrict__ outs,
          int it)
{
    int r = blockIdx.x;
    int tid = threadIdx.x;
    const float* row = in + (size_t)r*DM;
    float4 v = *(const float4*)(row + tid*4);
    float s  = v.x + v.y + v.z + v.w;
    float sq = v.x*v.x + v.y*v.y + v.z*v.z + v.w*v.w;
    #pragma unroll
    for (int o = 16; o; o >>= 1) {
        s  += __shfl_xor_sync(0xffffffffu, s,  o);
        sq += __shfl_xor_sync(0xffffffffu, sq, o);
    }
    __shared__ float ss[4], ssq[4];
    if ((tid & 31) == 0) { ss[tid >> 5] = s; ssq[tid >> 5] = sq; }
    __syncthreads();
    s  = ss[0] + ss[1] + ss[2] + ss[3];
    sq = ssq[0] + ssq[1] + ssq[2] + ssq[3];
    float mean = s * (1.f/512.f);
    float var  = sq * (1.f/512.f) - mean*mean;
    float inv  = rsqrtf(var + 1e-5f);
    int b = r >> 9, t = r & 511;
    size_t orow = ((size_t)b*PRED + (size_t)it*SEQ + t)*DM;
    int c = tid*4;
    float4 wv = *(const float4*)(w + c);
    float4 bv = *(const float4*)(bsrc + c);
    float4 res;
    res.x = (v.x - mean)*inv*wv.x + bv.x;
    res.y = (v.y - mean)*inv*wv.y + bv.y;
    res.z = (v.z - mean)*inv*wv.z + bv.z;
    res.w = (v.w - mean)*inv*wv.w + bv.w;
    *(float4*)(cur + (size_t)r*DM + c) = res;
    *(float4*)(outs + orow + c) = res;
}

// ---------------- host launcher -------------------------------------------------
extern "C" void kernel_launch(void* const* d_in, const int* in_sizes, int n_in,
                              void* d_out, int out_size)
{
    (void)in_sizes; (void)n_in; (void)out_size;
    const float* x_enc      = (const float*)d_in[0];
    const float* x_mark_enc = (const float*)d_in[1];
    const float* conv_emb_w = (const float*)d_in[4];
    const float* temp_w     = (const float*)d_in[5];
    const float* in_proj_w  = (const float*)d_in[6];
    const float* conv1d_w   = (const float*)d_in[7];
    const float* conv1d_b   = (const float*)d_in[8];
    const float* x_proj_w   = (const float*)d_in[9];
    const float* dt_proj_w  = (const float*)d_in[10];
    const float* dt_proj_b  = (const float*)d_in[11];
    const float* A_log      = (const float*)d_in[12];
    const float* D_in       = (const float*)d_in[13];
    const float* out_proj_w = (const float*)d_in[14];
    const float* ln_w       = (const float*)d_in[15];
    const float* ln_b       = (const float*)d_in[16];
    const float* head_w     = (const float*)d_in[17];

    float *emb, *xz, *xb, *xdbc, *dtb, *yb, *mo, *cur, *outs, *pe, *im, *wemb;
    __nv_bfloat16 *a3, *wi3, *wo3, *wx3;
    cudaGetSymbolAddress((void**)&emb,  g_emb);
    cudaGetSymbolAddress((void**)&xz,   g_xz);
    cudaGetSymbolAddress((void**)&xb,   g_x);
    cudaGetSymbolAddress((void**)&xdbc, g_xdbc);
    cudaGetSymbolAddress((void**)&dtb,  g_dt);
    cudaGetSymbolAddress((void**)&yb,   g_y);
    cudaGetSymbolAddress((void**)&mo,   g_mo);
    cudaGetSymbolAddress((void**)&cur,  g_cur);
    cudaGetSymbolAddress((void**)&outs, g_outs);
    cudaGetSymbolAddress((void**)&pe,   g_pe);
    cudaGetSymbolAddress((void**)&im,   g_im);
    cudaGetSymbolAddress((void**)&wemb, g_wemb);
    cudaGetSymbolAddress((void**)&a3,   g_a3);
    cudaGetSymbolAddress((void**)&wi3,  g_wi3);
    cudaGetSymbolAddress((void**)&wo3,  g_wo3);
    cudaGetSymbolAddress((void**)&wx3,  g_wx3);

    const int SMEM_MMA = 65536;
    cudaFuncSetAttribute(gemm_mma, cudaFuncAttributeMaxDynamicSharedMemorySize, SMEM_MMA);

    // ---- weight splits ----
    split3W_kernel<<<(2*DI*DM + 255)/256, 256>>>(in_proj_w,  wi3, 2*DI, 2*DI, DM);
    split3W_kernel<<<(DM*DI   + 255)/256, 256>>>(out_proj_w, wo3, DM,   DM,   DI);
    split3W_kernel<<<(128*DI  + 255)/256, 256>>>(x_proj_w,   wx3, 96,   128,  DI);

    // ---- embedding ----
    pe_kernel<<<(SEQ*DM + 511)/512, 512>>>(pe);
    im2col_kernel<<<(NTOK*KEMB + 255)/256, 256>>>(im, x_enc, x_mark_enc);
    wemb_kernel<<<(DM*KEMB + 255)/256, 256>>>(wemb, conv_emb_w, temp_w);
    gemm_tn<2><<<dim3(DM/64, NTOK/64), 256>>>(im, KEMB, wemb, nullptr, pe, emb,
                                              NTOK, DM, KEMB);

    // ---- 2 mamba blocks ----
    const float* curin = emb;
    for (int it = 0; it < 2; ++it) {
        // in_proj: [8192,2048] = curin[8192,512] @ W[2048,512]^T   (K3 = 1536)
        split3A_kernel<<<(NTOK*DM + 255)/256, 256>>>(curin, a3, NTOK*DM, DM);
        gemm_mma<<<dim3(2*DI/128, NTOK/128), 256, SMEM_MMA>>>(
            a3, wi3, xz, 3*DM, 2*DI, 2*DI);

        conv_silu_kernel<<<(NTOK*DI + 255)/256, 256>>>(xz, conv1d_w, conv1d_b, xb);

        // x_proj: [8192,96] = xb[8192,1024] @ W[96,1024]^T   (K3 = 3072)
        split3A_kernel<<<(NTOK*DI + 255)/256, 256>>>(xb, a3, NTOK*DI, DI);
        gemm_mma<<<dim3(1, NTOK/128), 256, SMEM_MMA>>>(
            a3, wx3, xdbc, 3*DI, 96, 96);

        gemm_tn<1><<<dim3(DI/64, NTOK/64), 256>>>(xdbc, 96, dt_proj_w, dt_proj_b,
                                                  nullptr, dtb, NTOK, DI, 32);
        scan_kernel<<<dim3(DI/128, BSZ), 512>>>(dtb, xdbc, xb, xz, A_log, D_in, yb);

        // out_proj: [8192,512] = yb[8192,1024] @ W[512,1024]^T   (K3 = 3072)
        split3A_kernel<<<(NTOK*DI + 255)/256, 256>>>(yb, a3, NTOK*DI, DI);
        gemm_mma<<<dim3(DM/128, NTOK/128), 256, SMEM_MMA>>>(
            a3, wo3, mo, 3*DI, DM, DM);

        ln_kernel<<<NTOK, 128>>>(mo, ln_w, ln_b, cur, outs, it);
        curin = cur;
    }

    // ---- head ----
    gemm_tn<0><<<dim3(1, (BSZ*PRED)/64), 256>>>(outs, DM, head_w, nullptr, nullptr,
                                                (float*)d_out, BSZ*PRED, 32, DM);
}

// round 10
// speedup vs baseline: 1.7777x; 1.5350x over previous
#include <cuda_runtime.h>
#include <cuda_bf16.h>
#include <math.h>
#include <stdint.h>

#define BSZ 16
#define SEQ 512
#define DM  512
#define DI  1024
#define DS  32
#define NTOK (BSZ*SEQ)        // 8192
#define KEMB 112              // 96 (conv im2col) + 4 (mark) + 12 zero pad -> %16==0
#define PRED 1024

// ---------------- scratch (static device globals; no runtime alloc) -------------
__device__ float g_xz  [(size_t)NTOK*2*DI];
__device__ float g_x   [NTOK*DI];
__device__ float g_xdbc[NTOK*96];
__device__ float g_dt  [NTOK*DI];
__device__ float g_mo  [NTOK*DM];
__device__ float g_outs[(size_t)BSZ*PRED*DM];
__device__ float g_pe  [SEQ*DM];
__device__ float g_im  [NTOK*KEMB];
__device__ float g_wemb[DM*KEMB];

// bf16 K3-concat buffers:  A3 = [hi | lo | hi],  W3 = [hi | hi | lo]
__device__ __nv_bfloat16 g_a3 [(size_t)NTOK*3*DI];          // up to 8192 x 3072
__device__ __nv_bfloat16 g_wi3[(size_t)2*DI*3*DM];          // 2048 x 1536
__device__ __nv_bfloat16 g_wo3[(size_t)DM*3*DI];            // 512 x 3072
__device__ __nv_bfloat16 g_wx3[(size_t)128*3*DI];           // 128(pad) x 3072

// ================= PTX helpers (baseline sm_80+ ISA only) =======================
__device__ __forceinline__ uint32_t smem_u32(const void* p) {
    uint32_t a;
    asm("{ .reg .u64 t; cvta.to.shared.u64 t, %1; cvt.u32.u64 %0, t; }" : "=r"(a) : "l"(p));
    return a;
}
#define CP_ASYNC16(dst, src) \
    asm volatile("cp.async.cg.shared.global [%0], [%1], 16;" :: "r"(dst), "l"(src))
#define CP_COMMIT() asm volatile("cp.async.commit_group;" ::: "memory")
#define CP_WAIT(n)  asm volatile("cp.async.wait_group %0;" :: "n"(n) : "memory")

__device__ __forceinline__ uint32_t pack_bf2(float x, float y) {
    __nv_bfloat162 t = __floats2bfloat162_rn(x, y);
    return *reinterpret_cast<uint32_t*>(&t);
}

// ---------------- fp32 -> bf16 hi/lo split for weights --------------------------
__global__ void split3W_kernel(const float* __restrict__ in,
                               __nv_bfloat16* __restrict__ out,
                               int N, int Npad, int K)
{
    int i = blockIdx.x * blockDim.x + threadIdx.x;
    if (i >= Npad*K) return;
    int n = i / K, k = i - n*K;
    float v = (n < N) ? in[(size_t)n*K + k] : 0.f;
    __nv_bfloat16 h = __float2bfloat16(v);
    __nv_bfloat16 l = __float2bfloat16(v - __bfloat162float(h));
    size_t base = (size_t)n*3*K + k;
    out[base]       = h;
    out[base + K]   = h;
    out[base + 2*K] = l;
}

// ---------------- warp-mma bf16 GEMM: C[M,N] = A3[M,K3] * W3[N,K3]^T ------------
// CTA tile 128x128, 8 warps (warp tile 64x32). K chunks of 64 bf16, XOR-swizzled
// SMEM, 3-stage cp.async ring (one barrier per chunk), fp32 register accum.
__global__ void __launch_bounds__(256, 2)
gemm_mma(const __nv_bfloat16* __restrict__ A, const __nv_bfloat16* __restrict__ W,
         float* __restrict__ C, int K3, int ldc, int nvalid)
{
    extern __shared__ char sm[];
    const uint32_t sbase = smem_u32(sm);
    const int tid  = threadIdx.x, lane = tid & 31, wid = tid >> 5;
    const int m0 = blockIdx.y * 128, n0 = blockIdx.x * 128;
    const int wm = (wid >> 2) * 64, wn = (wid & 3) * 32;
    const int NC = K3 >> 6;

    float acc[4][4][4];
    #pragma unroll
    for (int i = 0; i < 4; ++i)
        #pragma unroll
        for (int j = 0; j < 4; ++j)
            #pragma unroll
            for (int q = 0; q < 4; ++q) acc[i][j][q] = 0.f;

    // stage s: A tile at s*32768, W tile at s*32768 + 16384 (each 128 rows x 128B)
    auto issue = [&](int c, int s) {
        uint32_t sA = sbase + s*32768;
        uint32_t sW = sA + 16384;
        #pragma unroll
        for (int i = 0; i < 4; ++i) {
            int u = tid + i*256;
            int r = u >> 3, un = u & 7;
            uint32_t d = sA + r*128 + ((un ^ (r & 7)) << 4);
            CP_ASYNC16(d, A + (size_t)(m0 + r)*K3 + c*64 + un*8);
        }
        #pragma unroll
        for (int i = 0; i < 4; ++i) {
            int u = tid + i*256;
            int r = u >> 3, un = u & 7;
            uint32_t d = sW + r*128 + ((un ^ (r & 7)) << 4);
            CP_ASYNC16(d, W + (size_t)(n0 + r)*K3 + c*64 + un*8);
        }
        CP_COMMIT();
    };

    issue(0, 0);
    if (NC > 1) issue(1, 1);

    for (int c = 0; c < NC; ++c) {
        int s = c % 3;
        if (c == NC - 1) { CP_WAIT(0); } else { CP_WAIT(1); }
        __syncthreads();
        if (c + 2 < NC) issue(c + 2, (c + 2) % 3);

        uint32_t sA = sbase + s*32768;
        uint32_t sW = sA + 16384;
        #pragma unroll
        for (int ks = 0; ks < 4; ++ks) {
            uint32_t a[4][4];
            #pragma unroll
            for (int mt = 0; mt < 4; ++mt) {
                int r  = wm + mt*16 + (lane & 15);
                int un = ks*2 + (lane >> 4);
                uint32_t ad = sA + r*128 + ((un ^ (r & 7)) << 4);
                asm volatile("ldmatrix.sync.aligned.m8n8.x4.shared.b16 {%0,%1,%2,%3}, [%4];"
                    : "=r"(a[mt][0]), "=r"(a[mt][1]), "=r"(a[mt][2]), "=r"(a[mt][3])
                    : "r"(ad));
            }
            uint32_t b[4][2];
            #pragma unroll
            for (int p = 0; p < 2; ++p) {
                int n  = wn + p*16 + (lane & 7) + ((lane >> 4) << 3);
                int un = ks*2 + ((lane >> 3) & 1);
                uint32_t bd = sW + n*128 + ((un ^ (n & 7)) << 4);
                asm volatile("ldmatrix.sync.aligned.m8n8.x4.shared.b16 {%0,%1,%2,%3}, [%4];"
                    : "=r"(b[p*2][0]), "=r"(b[p*2][1]), "=r"(b[p*2+1][0]), "=r"(b[p*2+1][1])
                    : "r"(bd));
            }
            #pragma unroll
            for (int mt = 0; mt < 4; ++mt)
                #pragma unroll
                for (int nt = 0; nt < 4; ++nt)
                    asm volatile(
                        "mma.sync.aligned.m16n8k16.row.col.f32.bf16.bf16.f32 "
                        "{%0,%1,%2,%3}, {%4,%5,%6,%7}, {%8,%9}, {%0,%1,%2,%3};"
                        : "+f"(acc[mt][nt][0]), "+f"(acc[mt][nt][1]),
                          "+f"(acc[mt][nt][2]), "+f"(acc[mt][nt][3])
                        : "r"(a[mt][0]), "r"(a[mt][1]), "r"(a[mt][2]), "r"(a[mt][3]),
                          "r"(b[nt][0]), "r"(b[nt][1]));
        }
        __syncthreads();
    }

    // epilogue: c0,c1 -> row lane>>2, cols (lane&3)*2..+1; c2,c3 -> row +8
    #pragma unroll
    for (int mt = 0; mt < 4; ++mt) {
        int r0 = m0 + wm + mt*16 + (lane >> 2);
        #pragma unroll
        for (int nt = 0; nt < 4; ++nt) {
            int col = n0 + wn + nt*8 + (lane & 3)*2;
            if (col < nvalid) {
                *(float2*)(C + (size_t)r0*ldc + col) =
                    make_float2(acc[mt][nt][0], acc[mt][nt][1]);
                *(float2*)(C + (size_t)(r0+8)*ldc + col) =
                    make_float2(acc[mt][nt][2], acc[mt][nt][3]);
            }
        }
    }
}

// ---------------- positional embedding (fp32) -----------------------------------
__global__ void pe_kernel(float* __restrict__ pe) {
    int idx = blockIdx.x * blockDim.x + threadIdx.x;
    if (idx >= SEQ*DM) return;
    int t = idx >> 9;           // /512
    int o = idx & 511;
    int j2 = o & ~1;
    float div = expf(-(float)j2 * (logf(10000.0f) / (float)DM));
    float ang = (float)t * div;
    pe[idx] = (o & 1) ? cosf(ang) : sinf(ang);
}

// ---------------- im2col for the embed conv (+marks, zero pad) ------------------
__global__ void im2col_kernel(float* __restrict__ im,
                              const float* __restrict__ x_enc,
                              const float* __restrict__ x_mark) {
    int idx = blockIdx.x * blockDim.x + threadIdx.x;
    if (idx >= NTOK*KEMB) return;
    int n = idx / KEMB;
    int c = idx - n*KEMB;
    int b = n >> 9, t = n & 511;
    float v = 0.f;
    if (c < 96) {
        int k = c >> 5;
        int i = c & 31;
        int tt = t + k - 2; if (tt < 0) tt = 0;
        v = x_enc[(size_t)(b*SEQ + tt)*32 + i];
    } else if (c < 100) {
        v = x_mark[(size_t)n*4 + (c - 96)];
    }
    im[idx] = v;
}

__global__ void wemb_kernel(float* __restrict__ wemb,
                            const float* __restrict__ conv_w,
                            const float* __restrict__ temp_w) {
    int idx = blockIdx.x * blockDim.x + threadIdx.x;
    if (idx >= DM*KEMB) return;
    int o = idx / KEMB;
    int c = idx - o*KEMB;
    float v = 0.f;
    if (c < 96) {
        int k = c >> 5;
        int i = c & 31;
        v = conv_w[(size_t)(o*32 + i)*3 + k];
    } else if (c < 100) {
        v = temp_w[o*4 + (c - 96)];
    }
    wemb[idx] = v;
}

// ---------------- SIMT tiled GEMM (small GEMMs): C = A * W^T --------------------
// EP: 0 = none, 1 = +bias then softplus,
//     3 = += aux[(m%512)*N+n], then write ONLY bf16 hi/lo/hi split to C3
template<int EP>
__global__ void __launch_bounds__(256)
gemm_tn(const float* __restrict__ A, int lda,
        const float* __restrict__ W,
        const float* __restrict__ bias,
        const float* __restrict__ aux,
        float* __restrict__ C,
        __nv_bfloat16* __restrict__ C3,
        int M, int N, int K)
{
    __shared__ __align__(16) float As[16][68];
    __shared__ __align__(16) float Ws[16][68];
    const int tx = threadIdx.x & 15;
    const int ty = threadIdx.x >> 4;
    const int m0 = blockIdx.y * 64;
    const int n0 = blockIdx.x * 64;
    const int lr = threadIdx.x >> 2;
    const int lc = (threadIdx.x & 3) * 4;

    float c[4][4];
    #pragma unroll
    for (int i = 0; i < 4; ++i)
        #pragma unroll
        for (int j = 0; j < 4; ++j) c[i][j] = 0.f;

    for (int k0 = 0; k0 < K; k0 += 16) {
        float4 av = make_float4(0.f,0.f,0.f,0.f);
        int am = m0 + lr;
        if (am < M) av = *(const float4*)(A + (size_t)am*lda + k0 + lc);
        As[lc+0][lr] = av.x; As[lc+1][lr] = av.y;
        As[lc+2][lr] = av.z; As[lc+3][lr] = av.w;

        float4 wv = make_float4(0.f,0.f,0.f,0.f);
        int wn = n0 + lr;
        if (wn < N) wv = *(const float4*)(W + (size_t)wn*K + k0 + lc);
        Ws[lc+0][lr] = wv.x; Ws[lc+1][lr] = wv.y;
        Ws[lc+2][lr] = wv.z; Ws[lc+3][lr] = wv.w;
        __syncthreads();

        #pragma unroll
        for (int kk = 0; kk < 16; ++kk) {
            float4 a4 = *(const float4*)&As[kk][ty*4];
            float4 b4 = *(const float4*)&Ws[kk][tx*4];
            c[0][0] = fmaf(a4.x, b4.x, c[0][0]);
            c[0][1] = fmaf(a4.x, b4.y, c[0][1]);
            c[0][2] = fmaf(a4.x, b4.z, c[0][2]);
            c[0][3] = fmaf(a4.x, b4.w, c[0][3]);
            c[1][0] = fmaf(a4.y, b4.x, c[1][0]);
            c[1][1] = fmaf(a4.y, b4.y, c[1][1]);
            c[1][2] = fmaf(a4.y, b4.z, c[1][2]);
            c[1][3] = fmaf(a4.y, b4.w, c[1][3]);
            c[2][0] = fmaf(a4.z, b4.x, c[2][0]);
            c[2][1] = fmaf(a4.z, b4.y, c[2][1]);
            c[2][2] = fmaf(a4.z, b4.z, c[2][2]);
            c[2][3] = fmaf(a4.z, b4.w, c[2][3]);
            c[3][0] = fmaf(a4.w, b4.x, c[3][0]);
            c[3][1] = fmaf(a4.w, b4.y, c[3][1]);
            c[3][2] = fmaf(a4.w, b4.z, c[3][2]);
            c[3][3] = fmaf(a4.w, b4.w, c[3][3]);
        }
        __syncthreads();
    }

    #pragma unroll
    for (int i = 0; i < 4; ++i) {
        int m = m0 + ty*4 + i;
        if (m >= M) continue;
        #pragma unroll
        for (int j = 0; j < 4; ++j) {
            int n = n0 + tx*4 + j;
            if (n >= N) continue;
            float v = c[i][j];
            if (EP == 1) {
                v += bias[n];
                v = (v > 20.f) ? v : log1pf(__expf(v));
                C[(size_t)m*N + n] = v;
            } else if (EP == 3) {
                v += aux[(size_t)(m & 511)*N + n];
                __nv_bfloat16 h = __float2bfloat16(v);
                __nv_bfloat16 l = __float2bfloat16(v - __bfloat162float(h));
                size_t base = (size_t)m*3*N + n;
                C3[base]       = h;
                C3[base + N]   = l;
                C3[base + 2*N] = h;
            } else {
                C[(size_t)m*N + n] = v;
            }
        }
    }
}

// ---------------- depthwise causal conv1d (k=4) + SiLU + fused bf16 split -------
__global__ void conv_silu_kernel(const float* __restrict__ xz,
                                 const float* __restrict__ w,
                                 const float* __restrict__ bias,
                                 float* __restrict__ out,
                                 __nv_bfloat16* __restrict__ a3)
{
    int idx = blockIdx.x * blockDim.x + threadIdx.x;
    if (idx >= NTOK*DI) return;
    int d = idx & (DI-1);
    int n = idx >> 10;
    int t = n & 511;
    float s = bias[d];
    const float* wd = w + d*4;
    #pragma unroll
    for (int k = 0; k < 4; ++k) {
        int tau = t - 3 + k;
        if (tau >= 0)
            s = fmaf(wd[k], xz[(size_t)(n + k - 3)*(2*DI) + d], s);
    }
    float sil = s / (1.f + __expf(-s));
    out[idx] = sil;
    __nv_bfloat16 h = __float2bfloat16(sil);
    __nv_bfloat16 l = __float2bfloat16(sil - __bfloat162float(h));
    size_t base = (size_t)n*3*DI + d;
    a3[base]        = h;
    a3[base + DI]   = l;
    a3[base + 2*DI] = h;
}

// ---------------- selective scan (fused D-skip + z-gate + bf16 split out) -------
#define SCAN_STEP(J, BB, CC) { \
    float dA = __expf(dtv * a[J]); \
    h[J] = fmaf(dA, h[J], kk * (BB)); \
    acc = fmaf(h[J], (CC), acc); }

__global__ void __launch_bounds__(512)
scan_kernel(const float* __restrict__ dt_,
            const float* __restrict__ xdbc,
            const float* __restrict__ x_,
            const float* __restrict__ xz,
            const float* __restrict__ A_log,
            const float* __restrict__ Dv,
            __nv_bfloat16* __restrict__ a3)
{
    const int b    = blockIdx.y;
    const int grp  = threadIdx.x >> 2;
    const int l4   = threadIdx.x & 3;
    const int d    = blockIdx.x * 128 + grp;
    const int s0   = l4 * 8;

    float a[8];
    #pragma unroll
    for (int j = 0; j < 8; ++j)
        a[j] = -__expf(A_log[d*DS + s0 + j]);

    float h[8];
    #pragma unroll
    for (int j = 0; j < 8; ++j) h[j] = 0.f;

    const float Dd = Dv[d];
    const float* dtp = dt_ + (size_t)b*SEQ*DI + d;
    const float* xp  = x_  + (size_t)b*SEQ*DI + d;
    const float* zp  = xz  + (size_t)b*SEQ*(2*DI) + DI + d;
    const float* bc  = xdbc + (size_t)b*SEQ*96;
    __nv_bfloat16* yp3 = a3 + (size_t)(b*SEQ)*3*DI + d;

    float dtv = dtp[0];
    float xv  = xp[0];
    float zv  = zp[0];
    float4 B0 = *(const float4*)(bc + 32 + s0);
    float4 B1 = *(const float4*)(bc + 36 + s0);
    float4 C0 = *(const float4*)(bc + 64 + s0);
    float4 C1 = *(const float4*)(bc + 68 + s0);

    for (int t = 0; t < SEQ; ++t) {
        int tn = (t + 1 < SEQ) ? t + 1 : t;
        float dtv_n = dtp[(size_t)tn*DI];
        float xv_n  = xp[(size_t)tn*DI];
        float zv_n  = zp[(size_t)tn*(2*DI)];
        float4 B0n = *(const float4*)(bc + tn*96 + 32 + s0);
        float4 B1n = *(const float4*)(bc + tn*96 + 36 + s0);
        float4 C0n = *(const float4*)(bc + tn*96 + 64 + s0);
        float4 C1n = *(const float4*)(bc + tn*96 + 68 + s0);

        float kk = dtv * xv;
        float acc = 0.f;
        SCAN_STEP(0, B0.x, C0.x)
        SCAN_STEP(1, B0.y, C0.y)
        SCAN_STEP(2, B0.z, C0.z)
        SCAN_STEP(3, B0.w, C0.w)
        SCAN_STEP(4, B1.x, C1.x)
        SCAN_STEP(5, B1.y, C1.y)
        SCAN_STEP(6, B1.z, C1.z)
        SCAN_STEP(7, B1.w, C1.w)

        acc += __shfl_xor_sync(0xffffffffu, acc, 1);
        acc += __shfl_xor_sync(0xffffffffu, acc, 2);

        if (l4 == 0) {
            float sil = zv / (1.f + __expf(-zv));
            float yv = (acc + xv * Dd) * sil;
            __nv_bfloat16 hh = __float2bfloat16(yv);
            __nv_bfloat16 ll = __float2bfloat16(yv - __bfloat162float(hh));
            size_t base = (size_t)t*3*DI;
            yp3[base]        = hh;
            yp3[base + DI]   = ll;
            yp3[base + 2*DI] = hh;
        }
        dtv = dtv_n; xv = xv_n; zv = zv_n;
        B0 = B0n; B1 = B1n; C0 = C0n; C1 = C1n;
    }
}

// ---------------- layernorm: writes outs (float) + a3 split (next iter) ---------
__global__ void __launch_bounds__(128)
ln_kernel(const float* __restrict__ in,
          const float* __restrict__ w,
          const float* __restrict__ bsrc,
          __nv_bfloat16* __restrict__ a3,
          float* __restrict__ outs,
          int it)
{
    int r = blockIdx.x;
    int tid = threadIdx.x;
    const float* row = in + (size_t)r*DM;
    float4 v = *(const float4*)(row + tid*4);
    float s  = v.x + v.y + v.z + v.w;
    float sq = v.x*v.x + v.y*v.y + v.z*v.z + v.w*v.w;
    #pragma unroll
    for (int o = 16; o; o >>= 1) {
        s  += __shfl_xor_sync(0xffffffffu, s,  o);
        sq += __shfl_xor_sync(0xffffffffu, sq, o);
    }
    __shared__ float ss[4], ssq[4];
    if ((tid & 31) == 0) { ss[tid >> 5] = s; ssq[tid >> 5] = sq; }
    __syncthreads();
    s  = ss[0] + ss[1] + ss[2] + ss[3];
    sq = ssq[0] + ssq[1] + ssq[2] + ssq[3];
    float mean = s * (1.f/512.f);
    float var  = sq * (1.f/512.f) - mean*mean;
    float inv  = rsqrtf(var + 1e-5f);
    int b = r >> 9, t = r & 511;
    size_t orow = ((size_t)b*PRED + (size_t)it*SEQ + t)*DM;
    int c = tid*4;
    float4 wv = *(const float4*)(w + c);
    float4 bv = *(const float4*)(bsrc + c);
    float4 res;
    res.x = (v.x - mean)*inv*wv.x + bv.x;
    res.y = (v.y - mean)*inv*wv.y + bv.y;
    res.z = (v.z - mean)*inv*wv.z + bv.z;
    res.w = (v.w - mean)*inv*wv.w + bv.w;
    *(float4*)(outs + orow + c) = res;

    // fused hi/lo/hi bf16 split into a3 (row stride 3*DM)
    __nv_bfloat16 hx = __float2bfloat16(res.x);
    __nv_bfloat16 hy = __float2bfloat16(res.y);
    __nv_bfloat16 hz = __float2bfloat16(res.z);
    __nv_bfloat16 hw = __float2bfloat16(res.w);
    uint2 hi2;
    hi2.x = pack_bf2(res.x, res.y);
    hi2.y = pack_bf2(res.z, res.w);
    uint2 lo2;
    lo2.x = pack_bf2(res.x - __bfloat162float(hx), res.y - __bfloat162float(hy));
    lo2.y = pack_bf2(res.z - __bfloat162float(hz), res.w - __bfloat162float(hw));
    __nv_bfloat16* arow = a3 + (size_t)r*3*DM;
    *(uint2*)(arow + c)        = hi2;
    *(uint2*)(arow + DM + c)   = lo2;
    *(uint2*)(arow + 2*DM + c) = hi2;
}

// ---------------- host launcher -------------------------------------------------
extern "C" void kernel_launch(void* const* d_in, const int* in_sizes, int n_in,
                              void* d_out, int out_size)
{
    (void)in_sizes; (void)n_in; (void)out_size;
    const float* x_enc      = (const float*)d_in[0];
    const float* x_mark_enc = (const float*)d_in[1];
    const float* conv_emb_w = (const float*)d_in[4];
    const float* temp_w     = (const float*)d_in[5];
    const float* in_proj_w  = (const float*)d_in[6];
    const float* conv1d_w   = (const float*)d_in[7];
    const float* conv1d_b   = (const float*)d_in[8];
    const float* x_proj_w   = (const float*)d_in[9];
    const float* dt_proj_w  = (const float*)d_in[10];
    const float* dt_proj_b  = (const float*)d_in[11];
    const float* A_log      = (const float*)d_in[12];
    const float* D_in       = (const float*)d_in[13];
    const float* out_proj_w = (const float*)d_in[14];
    const float* ln_w       = (const float*)d_in[15];
    const float* ln_b       = (const float*)d_in[16];
    const float* head_w     = (const float*)d_in[17];

    float *xz, *xb, *xdbc, *dtb, *mo, *outs, *pe, *im, *wemb;
    __nv_bfloat16 *a3, *wi3, *wo3, *wx3;
    cudaGetSymbolAddress((void**)&xz,   g_xz);
    cudaGetSymbolAddress((void**)&xb,   g_x);
    cudaGetSymbolAddress((void**)&xdbc, g_xdbc);
    cudaGetSymbolAddress((void**)&dtb,  g_dt);
    cudaGetSymbolAddress((void**)&mo,   g_mo);
    cudaGetSymbolAddress((void**)&outs, g_outs);
    cudaGetSymbolAddress((void**)&pe,   g_pe);
    cudaGetSymbolAddress((void**)&im,   g_im);
    cudaGetSymbolAddress((void**)&wemb, g_wemb);
    cudaGetSymbolAddress((void**)&a3,   g_a3);
    cudaGetSymbolAddress((void**)&wi3,  g_wi3);
    cudaGetSymbolAddress((void**)&wo3,  g_wo3);
    cudaGetSymbolAddress((void**)&wx3,  g_wx3);

    const int SMEM_MMA = 3*32768;      // 98304, 3-stage ring
    cudaFuncSetAttribute(gemm_mma, cudaFuncAttributeMaxDynamicSharedMemorySize, SMEM_MMA);

    // ---- weight splits ----
    split3W_kernel<<<(2*DI*DM + 255)/256, 256>>>(in_proj_w,  wi3, 2*DI, 2*DI, DM);
    split3W_kernel<<<(DM*DI   + 255)/256, 256>>>(out_proj_w, wo3, DM,   DM,   DI);
    split3W_kernel<<<(128*DI  + 255)/256, 256>>>(x_proj_w,   wx3, 96,   128,  DI);

    // ---- embedding (GEMM writes split directly into a3) ----
    pe_kernel<<<(SEQ*DM + 511)/512, 512>>>(pe);
    im2col_kernel<<<(NTOK*KEMB + 255)/256, 256>>>(im, x_enc, x_mark_enc);
    wemb_kernel<<<(DM*KEMB + 255)/256, 256>>>(wemb, conv_emb_w, temp_w);
    gemm_tn<3><<<dim3(DM/64, NTOK/64), 256>>>(im, KEMB, wemb, nullptr, pe,
                                              nullptr, a3, NTOK, DM, KEMB);

    // ---- 2 mamba blocks ----
    for (int it = 0; it < 2; ++it) {
        // in_proj: [8192,2048] = a3[8192,3*512] @ wi3[2048,3*512]^T
        gemm_mma<<<dim3(2*DI/128, NTOK/128), 256, SMEM_MMA>>>(
            a3, wi3, xz, 3*DM, 2*DI, 2*DI);

        // conv+SiLU writes xb (float, for scan) and a3 split (for x_proj)
        conv_silu_kernel<<<(NTOK*DI + 255)/256, 256>>>(xz, conv1d_w, conv1d_b,
                                                       xb, a3);

        // x_proj: [8192,96] = a3[8192,3*1024] @ wx3[128,3*1024]^T
        gemm_mma<<<dim3(1, NTOK/128), 256, SMEM_MMA>>>(
            a3, wx3, xdbc, 3*DI, 96, 96);

        gemm_tn<1><<<dim3(DI/64, NTOK/64), 256>>>(xdbc, 96, dt_proj_w, dt_proj_b,
                                                  nullptr, dtb, nullptr,
                                                  NTOK, DI, 32);

        // scan writes y split directly into a3 (for out_proj)
        scan_kernel<<<dim3(DI/128, BSZ), 512>>>(dtb, xdbc, xb, xz, A_log, D_in, a3);

        // out_proj: [8192,512] = a3[8192,3*1024] @ wo3[512,3*1024]^T
        gemm_mma<<<dim3(DM/128, NTOK/128), 256, SMEM_MMA>>>(
            a3, wo3, mo, 3*DI, DM, DM);

        // LN writes outs slice + a3 split (next iter's in_proj input)
        ln_kernel<<<NTOK, 128>>>(mo, ln_w, ln_b, a3, outs, it);
    }

    // ---- head ----
    gemm_tn<0><<<dim3(1, (BSZ*PRED)/64), 256>>>(outs, DM, head_w, nullptr, nullptr,
                                                (float*)d_out, nullptr,
                                                BSZ*PRED, 32, DM);
}